// round 2
// baseline (speedup 1.0000x reference)
#include <cuda_runtime.h>
#include <math.h>

#define TT 48
#define BB 16
#define EE 512
#define VV 50000
#define SS 40000
#define GG 32
#define KK 8
#define NC 20
#define ROWS (TT*BB)          // 768
#define NCAND (KK*GG)         // 256

// ---- scratch (no allocations allowed) ----
__device__ int g_topk[ROWS * KK];
__device__ int g_first_sense[ROWS];

__device__ __forceinline__ bool better(float v1, int i1, float v2, int i2) {
    // total order: value desc, index asc (matches lax.top_k / argmax tie-break)
    return (v1 > v2) || (v1 == v2 && i1 < i2);
}

// Merge my sorted-desc 8-list with xor-partner's; both end with top-8 of union.
__device__ __forceinline__ void warp_merge8(float tv[8], int ti[8], int off) {
    float pv[8]; int pi[8];
#pragma unroll
    for (int j = 0; j < 8; j++) {
        pv[j] = __shfl_xor_sync(0xffffffffu, tv[7 - j], off);
        pi[j] = __shfl_xor_sync(0xffffffffu, ti[7 - j], off);
    }
    // bitonic split: keep larger of (A[j], reversed-B[j]) -> top-8 multiset, bitonic
#pragma unroll
    for (int j = 0; j < 8; j++) {
        if (better(pv[j], pi[j], tv[j], ti[j])) { tv[j] = pv[j]; ti[j] = pi[j]; }
    }
    // bitonic merge network (desc), all static indices
    auto ce = [&](int p, int q) {
        if (better(tv[q], ti[q], tv[p], ti[p])) {
            float fv = tv[p]; tv[p] = tv[q]; tv[q] = fv;
            int iv = ti[p]; ti[p] = ti[q]; ti[q] = iv;
        }
    };
    ce(0,4); ce(1,5); ce(2,6); ce(3,7);
    ce(0,2); ce(1,3); ce(4,6); ce(5,7);
    ce(0,1); ce(2,3); ce(4,5); ce(6,7);
}

// ============================================================================
// Kernel B: per row (768 CTAs): stage row in SMEM, online logsumexp + top-8,
// then write predictions_globals = logit - lse. One DRAM read, one DRAM write.
// ============================================================================
extern __shared__ float smemB[];

__global__ __launch_bounds__(512, 1)
void softmax_topk_kernel(const float* __restrict__ logits, float* __restrict__ out_globals)
{
    const int row = blockIdx.x;
    const int tid = threadIdx.x;
    const int lane = tid & 31;
    const int wid = tid >> 5;   // 16 warps

    float* srow   = smemB;                         // VV floats
    float* s_wtv  = smemB + VV;                    // 16*8
    int*   s_wti  = (int*)(s_wtv + 16 * 8);        // 16*8
    float* s_wm   = (float*)(s_wti + 16 * 8);      // 16
    float* s_ws   = s_wm + 16;                     // 16
    float* s_lse  = s_ws + 16;                     // 1

    const float4* in4  = (const float4*)(logits + (size_t)row * VV);
    float4*       sr4  = (float4*)srow;

    float tv[8]; int ti[8];
#pragma unroll
    for (int j = 0; j < 8; j++) { tv[j] = -INFINITY; ti[j] = 0x7fffffff; }
    float kth = -INFINITY;
    float m = -INFINITY, s = 0.0f;

    // ---- pass 1: stream row, online (m,s), per-thread top-8 ----
    for (int i = tid; i < VV / 4; i += 512) {
        float4 q = in4[i];
        sr4[i] = q;
        float vals[4] = { q.x, q.y, q.z, q.w };
#pragma unroll
        for (int c = 0; c < 4; c++) {
            float v = vals[c];
            if (v > m) { s = s * __expf(m - v) + 1.0f; m = v; }
            else       { s += __expf(v - m); }
            if (v > kth) {
                float cv = v; int ci = 4 * i + c;
#pragma unroll
                for (int j = 0; j < 8; j++) {
                    if (cv > tv[j]) {  // strict > keeps earlier (smaller) index ahead on ties
                        float fv = tv[j]; int iv = ti[j];
                        tv[j] = cv; ti[j] = ci;
                        cv = fv; ci = iv;
                    }
                }
                kth = tv[7];
            }
        }
    }

    // ---- warp reduce top-8 + (m,s) ----
#pragma unroll
    for (int off = 1; off < 32; off <<= 1) warp_merge8(tv, ti, off);
#pragma unroll
    for (int off = 16; off; off >>= 1) {
        float m2 = __shfl_xor_sync(0xffffffffu, m, off);
        float s2 = __shfl_xor_sync(0xffffffffu, s, off);
        float M  = fmaxf(m, m2);
        s = s * __expf(m - M) + s2 * __expf(m2 - M);
        m = M;
    }
    if (lane == 0) {
        s_wm[wid] = m; s_ws[wid] = s;
#pragma unroll
        for (int j = 0; j < 8; j++) { s_wtv[wid * 8 + j] = tv[j]; s_wti[wid * 8 + j] = ti[j]; }
    }
    __syncthreads();

    // ---- block finalize (warp 0) ----
    if (wid == 0) {
        float fv[8]; int fi[8];
        if (lane < 16) {
#pragma unroll
            for (int j = 0; j < 8; j++) { fv[j] = s_wtv[lane * 8 + j]; fi[j] = s_wti[lane * 8 + j]; }
        } else {
#pragma unroll
            for (int j = 0; j < 8; j++) { fv[j] = -INFINITY; fi[j] = 0x7fffffff; }
        }
#pragma unroll
        for (int off = 1; off < 16; off <<= 1) warp_merge8(fv, fi, off);
        if (lane == 0) {
#pragma unroll
            for (int j = 0; j < 8; j++) g_topk[row * KK + j] = fi[j];
            float M = s_wm[0], S = s_ws[0];
#pragma unroll
            for (int w = 1; w < 16; w++) {
                float m2 = s_wm[w], s2 = s_ws[w];
                float Mn = fmaxf(M, m2);
                S = S * __expf(M - Mn) + s2 * __expf(m2 - Mn);
                M = Mn;
            }
            *s_lse = M + logf(S);
        }
    }
    __syncthreads();
    const float lse = *s_lse;

    // ---- pass 2: write output from SMEM (no second DRAM read) ----
    float4* o4 = (float4*)(out_globals + (size_t)row * VV);
    for (int i = tid; i < VV / 4; i += 512) {
        float4 q = sr4[i];
        q.x -= lse; q.y -= lse; q.z -= lse; q.w -= lse;
        o4[i] = q;
    }
}

// ============================================================================
// Kernel D: per (t,b) row: build loc_ctx (window sum), score 256 candidate
// senses by dot(loc, SC[s]) / max(||SC[s]||, eps), argmax (first-index ties).
// ============================================================================
__global__ __launch_bounds__(256)
void sense_argmax_kernel(const float* __restrict__ word,
                         const float* __restrict__ prev,
                         const float* __restrict__ locin,
                         const float* __restrict__ SC,
                         const int*   __restrict__ neigh)
{
    __shared__ float s_loc[EE];
    __shared__ int   s_tk[KK];
    __shared__ float s_bv[8];
    __shared__ int   s_bc[8];

    const int row = blockIdx.x;
    const int t = row / BB, b = row % BB;
    const int tid = threadIdx.x;

    // loc_ctx[t,b,:] = location_context + (sum of 20 embeddings ending at word[t]) / 20
#pragma unroll
    for (int half = 0; half < 2; half++) {
        int e = tid + half * 256;
        float acc = 0.0f;
#pragma unroll
        for (int j = 0; j < NC; j++) {
            int cj = t + TT - NC + 1 + j;    // t+29 .. t+48
            const float* src = (cj < TT) ? prev : word;
            int r = (cj < TT) ? cj : (cj - TT);
            acc += src[((size_t)r * BB + b) * EE + e];
        }
        s_loc[e] = locin[(size_t)row * EE + e] + acc * (1.0f / NC);
    }
    if (tid < KK) s_tk[tid] = g_topk[row * KK + tid];
    __syncthreads();

    const int wid = tid >> 5, lane = tid & 31;
    const float4* loc4 = (const float4*)s_loc;

    float bestv = -INFINITY; int bestc = 0x7fffffff;
    const int tkw = s_tk[wid];   // this warp handles candidates [wid*32, wid*32+32)
    for (int g = 0; g < 32; g++) {
        const int c = wid * 32 + g;
        const int sense = neigh[(size_t)tkw * GG + g];
        const float4* sc4 = (const float4*)(SC + (size_t)sense * EE);
        float d = 0.0f, nb = 0.0f;
#pragma unroll
        for (int u = 0; u < 4; u++) {
            float4 bq = sc4[u * 32 + lane];
            float4 aq = loc4[u * 32 + lane];
            d  = fmaf(aq.x, bq.x, d);  d  = fmaf(aq.y, bq.y, d);
            d  = fmaf(aq.z, bq.z, d);  d  = fmaf(aq.w, bq.w, d);
            nb = fmaf(bq.x, bq.x, nb); nb = fmaf(bq.y, bq.y, nb);
            nb = fmaf(bq.z, bq.z, nb); nb = fmaf(bq.w, bq.w, nb);
        }
#pragma unroll
        for (int off = 16; off; off >>= 1) {
            d  += __shfl_xor_sync(0xffffffffu, d,  off);
            nb += __shfl_xor_sync(0xffffffffu, nb, off);
        }
        float score = d / fmaxf(sqrtf(nb), 1e-8f);
        if (better(score, c, bestv, bestc)) { bestv = score; bestc = c; }
    }
    if (lane == 0) { s_bv[wid] = bestv; s_bc[wid] = bestc; }
    __syncthreads();
    if (tid == 0) {
        float bv = s_bv[0]; int bc = s_bc[0];
#pragma unroll
        for (int w = 1; w < 8; w++)
            if (better(s_bv[w], s_bc[w], bv, bc)) { bv = s_bv[w]; bc = s_bc[w]; }
        g_first_sense[row] = neigh[(size_t)s_tk[bc >> 5] * GG + (bc & 31)];
    }
}

// ============================================================================
// Kernel E1/E2: predictions_senses = log(eps) everywhere, log(chosen) at winner
// ============================================================================
__global__ void fill_senses_kernel(float* __restrict__ out_senses, float val, int n4)
{
    float4 q = { val, val, val, val };
    float4* o = (float4*)out_senses;
    for (int i = blockIdx.x * blockDim.x + threadIdx.x; i < n4; i += gridDim.x * blockDim.x)
        o[i] = q;
}

__global__ void scatter_chosen_kernel(float* __restrict__ out_senses, float val)
{
    int row = blockIdx.x * blockDim.x + threadIdx.x;
    if (row < ROWS)
        out_senses[(size_t)row * SS + g_first_sense[row]] = val;
}

// ============================================================================
extern "C" void kernel_launch(void* const* d_in, const int* in_sizes, int n_in,
                              void* d_out, int out_size)
{
    (void)in_sizes; (void)n_in; (void)out_size;
    const float* word   = (const float*)d_in[0];
    const float* prev   = (const float*)d_in[1];
    const float* locc   = (const float*)d_in[2];
    const float* logits = (const float*)d_in[3];
    const float* SC     = (const float*)d_in[4];
    const int*   neigh  = (const int*)d_in[5];
    // d_in[6]=K, d_in[7]=num_C: fixed constants (8, 20) in this problem

    float* out_globals = (float*)d_out;
    float* out_senses  = out_globals + (size_t)ROWS * VV;

    const int smemB_bytes = (VV + 16 * 8 * 2 + 16 * 2 + 1) * 4;  // 201156 B
    cudaFuncSetAttribute(softmax_topk_kernel,
                         cudaFuncAttributeMaxDynamicSharedMemorySize, smemB_bytes);

    softmax_topk_kernel<<<ROWS, 512, smemB_bytes>>>(logits, out_globals);
    sense_argmax_kernel<<<ROWS, 256>>>(word, prev, locc, SC, neigh);

    const float log_eps    = logf(1e-8f);
    const float log_chosen = logf((float)(1.0 - 1e-8 * (double)(SS - 1)));
    fill_senses_kernel<<<2048, 256>>>(out_senses, log_eps, ROWS * SS / 4);
    scatter_chosen_kernel<<<(ROWS + 255) / 256, 256>>>(out_senses, log_chosen);
}

// round 4
// speedup vs baseline: 1.2451x; 1.2451x over previous
#include <cuda_runtime.h>
#include <math.h>
#include <stdint.h>

#define TT 48
#define BB 16
#define EE 512
#define VV 50000
#define SS 40000
#define GG 32
#define KK 8
#define NC 20
#define ROWS (TT*BB)          // 768
#define N4  (VV/4)            // 12500

// ---- scratch (no allocations allowed) ----
__device__ int g_topk[ROWS * KK];
__device__ int g_first_sense[ROWS];

__device__ __forceinline__ bool better(float v1, int i1, float v2, int i2) {
    // total order: value desc, index asc (matches lax.top_k / argmax tie-break)
    return (v1 > v2) || (v1 == v2 && i1 < i2);
}

// Merge my sorted-desc 8-list with xor-partner's; both end with top-8 of union.
__device__ __forceinline__ void warp_merge8(float tv[8], int ti[8], int off) {
    float pv[8]; int pi[8];
#pragma unroll
    for (int j = 0; j < 8; j++) {
        pv[j] = __shfl_xor_sync(0xffffffffu, tv[7 - j], off);
        pi[j] = __shfl_xor_sync(0xffffffffu, ti[7 - j], off);
    }
#pragma unroll
    for (int j = 0; j < 8; j++) {
        if (better(pv[j], pi[j], tv[j], ti[j])) { tv[j] = pv[j]; ti[j] = pi[j]; }
    }
    auto ce = [&](int p, int q) {
        if (better(tv[q], ti[q], tv[p], ti[p])) {
            float fv = tv[p]; tv[p] = tv[q]; tv[q] = fv;
            int iv = ti[p]; ti[p] = ti[q]; ti[q] = iv;
        }
    };
    ce(0,4); ce(1,5); ce(2,6); ce(3,7);
    ce(0,2); ce(1,3); ce(4,6); ce(5,7);
    ce(0,1); ce(2,3); ce(4,5); ce(6,7);
}

// ============================================================================
// Kernel B: per row (768 CTAs, 512 thr). Stage the 200KB row into SMEM with
// a 4-deep batched LDG->STS loop (high MLP, no dependency chain), computing
// max + per-thread top-8 on the staged values. Then sumexp with fixed max
// from SMEM, then write (logit - lse). One DRAM read + one write per row.
// ============================================================================
extern __shared__ float smemB[];

__global__ __launch_bounds__(512, 1)
void softmax_topk_kernel(const float* __restrict__ logits, float* __restrict__ out_globals)
{
    const int row = blockIdx.x;
    const int tid = threadIdx.x;
    const int lane = tid & 31;
    const int wid = tid >> 5;   // 16 warps

    float* srow   = smemB;                         // VV floats (200000 B)
    float* s_wtv  = smemB + VV;                    // 16*8
    int*   s_wti  = (int*)(s_wtv + 128);           // 16*8
    float* s_wm   = (float*)(s_wti + 128);         // 16
    float* s_ws   = s_wm + 16;                     // 16
    float* s_red  = s_ws + 16;                     // [0]=max, [1]=lse

    const float4* in4 = (const float4*)(logits + (size_t)row * VV);
    float4*       sr4 = (float4*)srow;

    float tv[8]; int ti[8];
#pragma unroll
    for (int j = 0; j < 8; j++) { tv[j] = -INFINITY; ti[j] = 0x7fffffff; }
    float kth = -INFINITY;
    float m = -INFINITY;

    // ---- pass 1: batched stage + scan (4 independent LDG.128 per batch) ----
    for (int base = 0; base < N4; base += 512 * 4) {
        float4 q[4]; int idx[4]; bool ok[4];
#pragma unroll
        for (int u = 0; u < 4; u++) {
            idx[u] = base + u * 512 + tid;
            ok[u] = idx[u] < N4;
            if (ok[u]) q[u] = in4[idx[u]];          // independent loads, batched
        }
#pragma unroll
        for (int u = 0; u < 4; u++) {
            if (!ok[u]) continue;
            sr4[idx[u]] = q[u];                      // fire-and-forget STS
            float vals[4] = { q[u].x, q[u].y, q[u].z, q[u].w };
            const int gbase = 4 * idx[u];
#pragma unroll
            for (int k = 0; k < 4; k++) {
                float v = vals[k];
                m = fmaxf(m, v);
                if (v > kth) {                       // cold path
                    float cv = v; int ci = gbase + k;
#pragma unroll
                    for (int j = 0; j < 8; j++) {
                        if (cv > tv[j]) {
                            float fv = tv[j]; int iv = ti[j];
                            tv[j] = cv; ti[j] = ci;
                            cv = fv; ci = iv;
                        }
                    }
                    kth = tv[7];
                }
            }
        }
    }

    // ---- reduce top-8 + max ----
#pragma unroll
    for (int off = 1; off < 32; off <<= 1) warp_merge8(tv, ti, off);
#pragma unroll
    for (int off = 16; off; off >>= 1)
        m = fmaxf(m, __shfl_xor_sync(0xffffffffu, m, off));
    if (lane == 0) {
        s_wm[wid] = m;
#pragma unroll
        for (int j = 0; j < 8; j++) { s_wtv[wid * 8 + j] = tv[j]; s_wti[wid * 8 + j] = ti[j]; }
    }
    __syncthreads();
    if (wid == 0) {
        float fv[8]; int fi[8];
        if (lane < 16) {
#pragma unroll
            for (int j = 0; j < 8; j++) { fv[j] = s_wtv[lane * 8 + j]; fi[j] = s_wti[lane * 8 + j]; }
        } else {
#pragma unroll
            for (int j = 0; j < 8; j++) { fv[j] = -INFINITY; fi[j] = 0x7fffffff; }
        }
#pragma unroll
        for (int off = 1; off < 16; off <<= 1) warp_merge8(fv, fi, off);
        if (lane == 0) {
#pragma unroll
            for (int j = 0; j < 8; j++) g_topk[row * KK + j] = fi[j];
            float M = s_wm[0];
#pragma unroll
            for (int w = 1; w < 16; w++) M = fmaxf(M, s_wm[w]);
            s_red[0] = M;
        }
    }
    __syncthreads();
    const float M = s_red[0];

    // ---- pass 2: sumexp with fixed max (MUFU throughput, from SMEM) ----
    float s = 0.0f;
    for (int i = tid; i < N4; i += 512) {
        float4 q = sr4[i];
        s += __expf(q.x - M) + __expf(q.y - M) + __expf(q.z - M) + __expf(q.w - M);
    }
#pragma unroll
    for (int off = 16; off; off >>= 1)
        s += __shfl_xor_sync(0xffffffffu, s, off);
    if (lane == 0) s_ws[wid] = s;
    __syncthreads();
    if (tid == 0) {
        float S = s_ws[0];
#pragma unroll
        for (int w = 1; w < 16; w++) S += s_ws[w];
        s_red[1] = M + logf(S);
    }
    __syncthreads();
    const float lse = s_red[1];

    // ---- pass 3: write output from SMEM ----
    float4* o4 = (float4*)(out_globals + (size_t)row * VV);
    for (int i = tid; i < N4; i += 512) {
        float4 q = sr4[i];
        q.x -= lse; q.y -= lse; q.z -= lse; q.w -= lse;
        o4[i] = q;
    }
}

// ============================================================================
// Kernel D: per (t,b) row: loc_ctx window, score 256 candidates by
// dot(loc, SC[s]) / max(||SC[s]||, eps), argmax with first-index tie-break.
// 2 senses in flight per warp-iteration for gather MLP.
// ============================================================================
__global__ __launch_bounds__(256)
void sense_argmax_kernel(const float* __restrict__ word,
                         const float* __restrict__ prev,
                         const float* __restrict__ locin,
                         const float* __restrict__ SC,
                         const int*   __restrict__ neigh)
{
    __shared__ float s_loc[EE];
    __shared__ int   s_tk[KK];
    __shared__ float s_bv[8];
    __shared__ int   s_bc[8];

    const int row = blockIdx.x;
    const int t = row / BB, b = row % BB;
    const int tid = threadIdx.x;

#pragma unroll
    for (int half = 0; half < 2; half++) {
        int e = tid + half * 256;
        float acc = 0.0f;
#pragma unroll
        for (int j = 0; j < NC; j++) {
            int cj = t + TT - NC + 1 + j;    // t+29 .. t+48
            const float* src = (cj < TT) ? prev : word;
            int r = (cj < TT) ? cj : (cj - TT);
            acc += src[((size_t)r * BB + b) * EE + e];
        }
        s_loc[e] = locin[(size_t)row * EE + e] + acc * (1.0f / NC);
    }
    if (tid < KK) s_tk[tid] = g_topk[row * KK + tid];
    __syncthreads();

    const int wid = tid >> 5, lane = tid & 31;
    const float4* loc4 = (const float4*)s_loc;

    float bestv = -INFINITY; int bestc = 0x7fffffff;
    const int tkw = s_tk[wid];
    for (int g = 0; g < 32; g += 2) {
        const int sense0 = neigh[(size_t)tkw * GG + g];
        const int sense1 = neigh[(size_t)tkw * GG + g + 1];
        const float4* b0 = (const float4*)(SC + (size_t)sense0 * EE);
        const float4* b1 = (const float4*)(SC + (size_t)sense1 * EE);
        float d0 = 0.f, n0 = 0.f, d1 = 0.f, n1 = 0.f;
#pragma unroll
        for (int u = 0; u < 4; u++) {
            float4 q0 = b0[u * 32 + lane];
            float4 q1 = b1[u * 32 + lane];
            float4 aq = loc4[u * 32 + lane];
            d0 = fmaf(aq.x, q0.x, d0); d0 = fmaf(aq.y, q0.y, d0);
            d0 = fmaf(aq.z, q0.z, d0); d0 = fmaf(aq.w, q0.w, d0);
            n0 = fmaf(q0.x, q0.x, n0); n0 = fmaf(q0.y, q0.y, n0);
            n0 = fmaf(q0.z, q0.z, n0); n0 = fmaf(q0.w, q0.w, n0);
            d1 = fmaf(aq.x, q1.x, d1); d1 = fmaf(aq.y, q1.y, d1);
            d1 = fmaf(aq.z, q1.z, d1); d1 = fmaf(aq.w, q1.w, d1);
            n1 = fmaf(q1.x, q1.x, n1); n1 = fmaf(q1.y, q1.y, n1);
            n1 = fmaf(q1.z, q1.z, n1); n1 = fmaf(q1.w, q1.w, n1);
        }
#pragma unroll
        for (int off = 16; off; off >>= 1) {
            d0 += __shfl_xor_sync(0xffffffffu, d0, off);
            n0 += __shfl_xor_sync(0xffffffffu, n0, off);
            d1 += __shfl_xor_sync(0xffffffffu, d1, off);
            n1 += __shfl_xor_sync(0xffffffffu, n1, off);
        }
        float sc0 = d0 / fmaxf(sqrtf(n0), 1e-8f);
        float sc1 = d1 / fmaxf(sqrtf(n1), 1e-8f);
        const int c0 = wid * 32 + g, c1 = c0 + 1;
        if (better(sc0, c0, bestv, bestc)) { bestv = sc0; bestc = c0; }
        if (better(sc1, c1, bestv, bestc)) { bestv = sc1; bestc = c1; }
    }
    if (lane == 0) { s_bv[wid] = bestv; s_bc[wid] = bestc; }
    __syncthreads();
    if (tid == 0) {
        float bv = s_bv[0]; int bc = s_bc[0];
#pragma unroll
        for (int w = 1; w < 8; w++)
            if (better(s_bv[w], s_bc[w], bv, bc)) { bv = s_bv[w]; bc = s_bc[w]; }
        g_first_sense[row] = neigh[(size_t)s_tk[bc >> 5] * GG + (bc & 31)];
    }
}

// ============================================================================
// Kernel E: predictions_senses — fill log(eps), patch chosen lane in-register.
// One write pass, no read-modify-write, single launch.
// ============================================================================
__global__ __launch_bounds__(256)
void senses_out_kernel(float* __restrict__ out_senses, float log_eps, float log_chosen)
{
    const int row = blockIdx.x;
    const int chosen = g_first_sense[row];
    const int ch4 = chosen >> 2, chc = chosen & 3;
    float4* o = (float4*)(out_senses + (size_t)row * SS);
    for (int i = threadIdx.x; i < SS / 4; i += 256) {
        float4 q = { log_eps, log_eps, log_eps, log_eps };
        if (i == ch4) ((float*)&q)[chc] = log_chosen;
        o[i] = q;
    }
}

// ============================================================================
extern "C" void kernel_launch(void* const* d_in, const int* in_sizes, int n_in,
                              void* d_out, int out_size)
{
    (void)in_sizes; (void)n_in; (void)out_size;
    const float* word   = (const float*)d_in[0];
    const float* prev   = (const float*)d_in[1];
    const float* locc   = (const float*)d_in[2];
    const float* logits = (const float*)d_in[3];
    const float* SC     = (const float*)d_in[4];
    const int*   neigh  = (const int*)d_in[5];

    float* out_globals = (float*)d_out;
    float* out_senses  = out_globals + (size_t)ROWS * VV;

    const int smemB_bytes = (VV + 128 * 2 + 16 * 2 + 2) * 4;  // ~201 KB
    cudaFuncSetAttribute(softmax_topk_kernel,
                         cudaFuncAttributeMaxDynamicSharedMemorySize, smemB_bytes);

    softmax_topk_kernel<<<ROWS, 512, smemB_bytes>>>(logits, out_globals);
    sense_argmax_kernel<<<ROWS, 256>>>(word, prev, locc, SC, neigh);

    const float log_eps    = logf(1e-8f);
    const float log_chosen = logf((float)(1.0 - 1e-8 * (double)(SS - 1)));
    senses_out_kernel<<<ROWS, 256>>>(out_senses, log_eps, log_chosen);
}